// round 14
// baseline (speedup 1.0000x reference)
#include <cuda_runtime.h>
#include <cuda_fp16.h>
#include <math.h>

// ---------------- scratch (no allocation allowed; __device__ globals) --------
#define MAX_N 100000
__device__ unsigned g_projh[MAX_N * 16]; // fp16 proj: [n][0:16]=z@W1a, [n][16:32]=z@W1b+b1 (6.4 MB)
__device__ uint4 g_zh[MAX_N * 16];       // z in fp16, 256B per node row (25.6 MB)
__device__ uint2 g_Bfrag[1024];          // W1 as mma B-fragments [ks][ns][lane] (8 KB)

// packed f32x2 ops (Blackwell — PTX-only)
#define FMA_F32X2(acc, a, b) \
    asm("fma.rn.f32x2 %0, %1, %2, %0;" : "+l"(acc) : "l"(a), "l"(b))
#define ADD_F32X2(out, a, b) \
    asm("add.rn.f32x2 %0, %1, %2;" : "=l"(out) : "l"(a), "l"(b))

__device__ __forceinline__ float2 cvt_h2(unsigned u) {
    __half2 h = *reinterpret_cast<__half2*>(&u);
    return __half22float2(h);
}
__device__ __forceinline__ unsigned pack_h2(float a, float b) {
    __half2 h = __floats2half2_rn(a, b);
    return *reinterpret_cast<unsigned*>(&h);
}

// ---------------- kernel 1: z -> fp16 copy + B-fragment table ----------------
// 2 uint4 outputs per thread (4 independent LDG.128 in flight). Block 0 also
// builds the m16n8k16 B fragments of Wc.
__global__ __launch_bounds__(256) void convert_kernel(
    const float* __restrict__ z, const float* __restrict__ W1, int N)
{
    int e0 = (blockIdx.x * blockDim.x + threadIdx.x) * 2;
    const float4* z4 = (const float4*)z;
    #pragma unroll
    for (int u = 0; u < 2; u++) {
        int e = e0 + u;
        if (e < N * 16) {
            float4 v0 = __ldg(z4 + 2 * (size_t)e);
            float4 v1 = __ldg(z4 + 2 * (size_t)e + 1);
            uint4 pk;
            pk.x = pack_h2(v0.x, v0.y);
            pk.y = pack_h2(v0.z, v0.w);
            pk.z = pack_h2(v1.x, v1.y);
            pk.w = pack_h2(v1.z, v1.w);
            g_zh[e] = pk;
        }
    }
    if (blockIdx.x == 0) {
        for (int i = threadIdx.x; i < 1024; i += blockDim.x) {
            int l  = i & 31;
            int ns = (i >> 5) & 3;
            int ks = i >> 7;
            int tg = l & 3, g = l >> 2;
            int n  = ns * 8 + g;
            int k0 = ks * 16 + tg * 2;
            auto wc = [&](int k) {
                return (n < 16) ? __ldg(W1 + k * 16 + n)
                                : __ldg(W1 + (128 + k) * 16 + (n - 16));
            };
            uint2 frag;
            frag.x = pack_h2(wc(k0),     wc(k0 + 1));
            frag.y = pack_h2(wc(k0 + 8), wc(k0 + 9));
            g_Bfrag[i] = frag;
        }
    }
}

// ---------------- kernel 2: proj via mma.sync m16n8k16 (HMMA) ----------------
// Block = 128 thr (4 warps), tile = 64 nodes. cp.async zh tile into smem with
// 272B pitch. Warp w computes nodes [w*16, w*16+16) x 32 cols: 8 k-steps x 4
// n-steps of mma. b1 folded into cols 16..31; result stored as packed fp16.
#define PITCH 272
__global__ __launch_bounds__(128) void proj_mma_kernel(
    const float* __restrict__ b1, int N)
{
    __shared__ __align__(16) char sA[64 * PITCH];    // 17408 B
    const int tid = threadIdx.x;
    const int node0 = blockIdx.x * 64;

    {
        unsigned sbase = (unsigned)__cvta_generic_to_shared(sA);
        const char* src0 = (const char*)g_zh;
        #pragma unroll
        for (int i = 0; i < 8; i++) {
            int c = tid + i * 128;
            int row = c >> 4, cc = c & 15;
            int node = min(node0 + row, N - 1);
            asm volatile("cp.async.cg.shared.global [%0], [%1], 16;"
                :: "r"(sbase + row * PITCH + cc * 16),
                   "l"(src0 + (size_t)node * 256 + cc * 16));
        }
        asm volatile("cp.async.commit_group;");
        asm volatile("cp.async.wait_group 0;");
    }
    __syncthreads();

    const int w = tid >> 5, l = tid & 31;
    const int g = l >> 2, tg = l & 3;

    float c0[4], c1[4], c2[4], c3[4];
    #pragma unroll
    for (int ns = 0; ns < 4; ns++) { c0[ns] = c1[ns] = c2[ns] = c3[ns] = 0.f; }

    const char* aR0 = sA + (w * 16 + g) * PITCH + tg * 4;
    const char* aR1 = aR0 + 8 * PITCH;

    #pragma unroll
    for (int ks = 0; ks < 8; ks++) {
        unsigned a0 = *(const unsigned*)(aR0 + ks * 32);
        unsigned a1 = *(const unsigned*)(aR1 + ks * 32);
        unsigned a2 = *(const unsigned*)(aR0 + ks * 32 + 16);
        unsigned a3 = *(const unsigned*)(aR1 + ks * 32 + 16);
        #pragma unroll
        for (int ns = 0; ns < 4; ns++) {
            uint2 b = g_Bfrag[(ks * 4 + ns) * 32 + l];
            asm volatile(
                "mma.sync.aligned.m16n8k16.row.col.f32.f16.f16.f32 "
                "{%0,%1,%2,%3}, {%4,%5,%6,%7}, {%8,%9}, {%0,%1,%2,%3};"
                : "+f"(c0[ns]), "+f"(c1[ns]), "+f"(c2[ns]), "+f"(c3[ns])
                : "r"(a0), "r"(a1), "r"(a2), "r"(a3), "r"(b.x), "r"(b.y));
        }
    }

    float2 bias2 = *(const float2*)(b1 + tg * 2);
    float2 bias3 = *(const float2*)(b1 + 8 + tg * 2);

    const int n0 = node0 + w * 16 + g;
    const int n1 = n0 + 8;
    #pragma unroll
    for (int ns = 0; ns < 4; ns++) {
        float bx = (ns == 2) ? bias2.x : (ns == 3) ? bias3.x : 0.f;
        float by = (ns == 2) ? bias2.y : (ns == 3) ? bias3.y : 0.f;
        int hoff = ns * 4 + tg;                      // half2 slot 0..15
        if (n0 < N)
            g_projh[(size_t)n0 * 16 + hoff] = pack_h2(c0[ns] + bx, c1[ns] + by);
        if (n1 < N)
            g_projh[(size_t)n1 * 16 + hoff] = pack_h2(c2[ns] + bx, c3[ns] + by);
    }
}

// ---------------- kernel 3: per-edge dual head (fp16 dot + fp16 proj) --------
// 8 lanes per edge, 4 edges/warp. zh gathers 256B/side; proj gathers now 4B
// per lane (fp16). (dot, t) reduced together as packed f32x2 over 3 rounds.
__global__ __launch_bounds__(256) void edge_kernel(
    const int* __restrict__ ei,            // int32 (jax x64 disabled)
    const float* __restrict__ W2,
    const float* __restrict__ b2,
    float* __restrict__ out,
    int E)
{
    const int group = (int)((blockIdx.x * blockDim.x + threadIdx.x) >> 3);  // edge id
    const int l = threadIdx.x & 7;
    const bool valid = (group < E);
    const int e = valid ? group : (E - 1);        // clamp; keep warp converged

    const int row = __ldg(ei + e);
    const int col = __ldg(ei + (size_t)E + e);

    uint4 A0 = __ldg(g_zh + (size_t)row * 16 + l);
    uint4 A1 = __ldg(g_zh + (size_t)row * 16 + 8 + l);
    uint4 B0 = __ldg(g_zh + (size_t)col * 16 + l);
    uint4 B1 = __ldg(g_zh + (size_t)col * 16 + 8 + l);

    unsigned long long dacc = 0ull;
    {
        float2 a, b;
        unsigned long long pa_, pb_;
        #define DOT_STEP(au, bu) \
            a = cvt_h2(au); b = cvt_h2(bu); \
            pa_ = *reinterpret_cast<unsigned long long*>(&a); \
            pb_ = *reinterpret_cast<unsigned long long*>(&b); \
            FMA_F32X2(dacc, pa_, pb_)
        DOT_STEP(A0.x, B0.x); DOT_STEP(A0.y, B0.y);
        DOT_STEP(A0.z, B0.z); DOT_STEP(A0.w, B0.w);
        DOT_STEP(A1.x, B1.x); DOT_STEP(A1.y, B1.y);
        DOT_STEP(A1.z, B1.z); DOT_STEP(A1.w, B1.w);
        #undef DOT_STEP
    }
    float2 dp = *reinterpret_cast<float2*>(&dacc);
    float dot = dp.x + dp.y;

    // MLP head: lane owns hidden units 2l, 2l+1 (fp16 proj; b1 pre-folded)
    unsigned pau = __ldg((const unsigned*)g_projh + (size_t)row * 16 + l);
    unsigned pbu = __ldg((const unsigned*)g_projh + (size_t)col * 16 + 8 + l);
    float2 pa = cvt_h2(pau);
    float2 pb = cvt_h2(pbu);
    float2 w2 = *(const float2*)(W2 + 2 * l);
    float h0 = fmaxf(pa.x + pb.x, 0.f);
    float h1 = fmaxf(pa.y + pb.y, 0.f);
    float t  = h0 * w2.x + h1 * w2.y;

    float2 pr = make_float2(dot, t);
    unsigned long long pk = *reinterpret_cast<unsigned long long*>(&pr);
    #pragma unroll
    for (int off = 4; off; off >>= 1) {
        unsigned long long other = __shfl_xor_sync(0xFFFFFFFFu, pk, off);
        ADD_F32X2(pk, pk, other);
    }

    if (l == 0 && valid) {
        float2 r = *reinterpret_cast<float2*>(&pk);
        out[e] = r.x;
        float x = r.y + __ldg(b2);
        out[(size_t)E + e] = fmaxf(x, 0.f) + log1pf(__expf(-fabsf(x)));
    }
}

// ---------------- launch ----------------------------------------------------
extern "C" void kernel_launch(void* const* d_in, const int* in_sizes, int n_in,
                              void* d_out, int out_size) {
    const float* z  = (const float*)d_in[0];      // [N,128] f32
    const int*   ei = (const int*)d_in[1];        // [2,E] int32
    const float* W1 = (const float*)d_in[2];      // [256,16]
    const float* b1 = (const float*)d_in[3];      // [16]
    const float* W2 = (const float*)d_in[4];      // [16,1]
    const float* b2 = (const float*)d_in[5];      // [1]
    float* out = (float*)d_out;                   // [2E]: adj_logits | weights

    const int N = in_sizes[0] / 128;
    const int E = in_sizes[1] / 2;

    convert_kernel<<<(N * 16 / 2 + 255) / 256, 256>>>(z, W1, N);
    proj_mma_kernel<<<(N + 63) / 64, 128>>>(b1, N);
    edge_kernel<<<((size_t)E * 8 + 255) / 256, 256>>>(ei, W2, b2, out, E);
}

// round 16
// speedup vs baseline: 1.5354x; 1.5354x over previous
#include <cuda_runtime.h>
#include <cuda_fp16.h>
#include <math.h>

// ---------------- scratch (no allocation allowed; __device__ globals) --------
#define MAX_N 100000
__device__ float g_proj[MAX_N * 32];   // [n][0:16]=z@W1a, [n][16:32]=z@W1b+b1 (12.8 MB)
__device__ uint4 g_zh[MAX_N * 16];     // z in fp16, 256B per node row (25.6 MB)
__device__ uint2 g_Bfrag[1024];        // W1 as mma B-fragments [ks][ns][lane] (8 KB)

// packed f32x2 ops (Blackwell — PTX-only)
#define FMA_F32X2(acc, a, b) \
    asm("fma.rn.f32x2 %0, %1, %2, %0;" : "+l"(acc) : "l"(a), "l"(b))
#define ADD_F32X2(out, a, b) \
    asm("add.rn.f32x2 %0, %1, %2;" : "=l"(out) : "l"(a), "l"(b))

__device__ __forceinline__ float2 cvt_h2(unsigned u) {
    __half2 h = *reinterpret_cast<__half2*>(&u);
    return __half22float2(h);
}
__device__ __forceinline__ unsigned pack_h2(float a, float b) {
    __half2 h = __floats2half2_rn(a, b);
    return *reinterpret_cast<unsigned*>(&h);
}

// ---------------- kernel 1: z -> fp16 copy + B-fragment table ----------------
// R12-proven (measured 11.9us, at its 77MB traffic floor). One uint4 per
// thread, fully coalesced. Block 0 also builds the m16n8k16 B fragments.
__global__ __launch_bounds__(256) void convert_kernel(
    const float* __restrict__ z, const float* __restrict__ W1, int N)
{
    int e = blockIdx.x * blockDim.x + threadIdx.x;
    if (e < N * 16) {
        const float4* z4 = (const float4*)z;
        float4 v0 = __ldg(z4 + 2 * (size_t)e);
        float4 v1 = __ldg(z4 + 2 * (size_t)e + 1);
        uint4 pk;
        pk.x = pack_h2(v0.x, v0.y);
        pk.y = pack_h2(v0.z, v0.w);
        pk.z = pack_h2(v1.x, v1.y);
        pk.w = pack_h2(v1.z, v1.w);
        g_zh[e] = pk;
    }
    if (blockIdx.x == 0) {
        for (int i = threadIdx.x; i < 1024; i += blockDim.x) {
            int l  = i & 31;
            int ns = (i >> 5) & 3;
            int ks = i >> 7;
            int tg = l & 3, g = l >> 2;
            int n  = ns * 8 + g;
            int k0 = ks * 16 + tg * 2;
            auto wc = [&](int k) {
                return (n < 16) ? __ldg(W1 + k * 16 + n)
                                : __ldg(W1 + (128 + k) * 16 + (n - 16));
            };
            uint2 frag;
            frag.x = pack_h2(wc(k0),     wc(k0 + 1));
            frag.y = pack_h2(wc(k0 + 8), wc(k0 + 9));
            g_Bfrag[i] = frag;
        }
    }
}

// ---------------- kernel 2: proj via mma.sync m16n8k16 (HMMA) ----------------
// R12-proven (~3.5us). Block = 128 thr, tile = 64 nodes, 272B-pitch smem,
// 8 k-steps x 4 n-steps, b1 folded into cols 16..31, f32 output.
#define PITCH 272
__global__ __launch_bounds__(128) void proj_mma_kernel(
    const float* __restrict__ b1, int N)
{
    __shared__ __align__(16) char sA[64 * PITCH];    // 17408 B
    const int tid = threadIdx.x;
    const int node0 = blockIdx.x * 64;

    {
        unsigned sbase = (unsigned)__cvta_generic_to_shared(sA);
        const char* src0 = (const char*)g_zh;
        #pragma unroll
        for (int i = 0; i < 8; i++) {
            int c = tid + i * 128;
            int row = c >> 4, cc = c & 15;
            int node = min(node0 + row, N - 1);
            asm volatile("cp.async.cg.shared.global [%0], [%1], 16;"
                :: "r"(sbase + row * PITCH + cc * 16),
                   "l"(src0 + (size_t)node * 256 + cc * 16));
        }
        asm volatile("cp.async.commit_group;");
        asm volatile("cp.async.wait_group 0;");
    }
    __syncthreads();

    const int w = tid >> 5, l = tid & 31;
    const int g = l >> 2, tg = l & 3;

    float c0[4], c1[4], c2[4], c3[4];
    #pragma unroll
    for (int ns = 0; ns < 4; ns++) { c0[ns] = c1[ns] = c2[ns] = c3[ns] = 0.f; }

    const char* aR0 = sA + (w * 16 + g) * PITCH + tg * 4;
    const char* aR1 = aR0 + 8 * PITCH;

    #pragma unroll
    for (int ks = 0; ks < 8; ks++) {
        unsigned a0 = *(const unsigned*)(aR0 + ks * 32);
        unsigned a1 = *(const unsigned*)(aR1 + ks * 32);
        unsigned a2 = *(const unsigned*)(aR0 + ks * 32 + 16);
        unsigned a3 = *(const unsigned*)(aR1 + ks * 32 + 16);
        #pragma unroll
        for (int ns = 0; ns < 4; ns++) {
            uint2 b = g_Bfrag[(ks * 4 + ns) * 32 + l];
            asm volatile(
                "mma.sync.aligned.m16n8k16.row.col.f32.f16.f16.f32 "
                "{%0,%1,%2,%3}, {%4,%5,%6,%7}, {%8,%9}, {%0,%1,%2,%3};"
                : "+f"(c0[ns]), "+f"(c1[ns]), "+f"(c2[ns]), "+f"(c3[ns])
                : "r"(a0), "r"(a1), "r"(a2), "r"(a3), "r"(b.x), "r"(b.y));
        }
    }

    float2 bias2 = *(const float2*)(b1 + tg * 2);
    float2 bias3 = *(const float2*)(b1 + 8 + tg * 2);

    const int n0 = node0 + w * 16 + g;
    const int n1 = n0 + 8;
    #pragma unroll
    for (int ns = 0; ns < 4; ns++) {
        float bx = (ns == 2) ? bias2.x : (ns == 3) ? bias3.x : 0.f;
        float by = (ns == 2) ? bias2.y : (ns == 3) ? bias3.y : 0.f;
        int coff = ns * 8 + tg * 2;
        if (n0 < N)
            *(float2*)(g_proj + (size_t)n0 * 32 + coff) =
                make_float2(c0[ns] + bx, c1[ns] + by);
        if (n1 < N)
            *(float2*)(g_proj + (size_t)n1 * 32 + coff) =
                make_float2(c2[ns] + bx, c3[ns] + by);
    }
}

// ---------------- kernel 3: per-edge dual head (fp16 dot, 8 edges/warp) ------
// 4 lanes per edge. Load k: lane l takes chunk k*4+l (contiguous 64B per
// group per instruction -> 4 lines/warp = line floor). 16 FMA2 dot per lane.
// Lane owns 4 hidden units (float4 proj loads). 2 packed shuffle rounds.
__global__ __launch_bounds__(256) void edge_kernel(
    const int* __restrict__ ei,            // int32 (jax x64 disabled)
    const float* __restrict__ W2,
    const float* __restrict__ b2,
    float* __restrict__ out,
    int E)
{
    const int group = (int)((blockIdx.x * blockDim.x + threadIdx.x) >> 2);  // edge id
    const int l = threadIdx.x & 3;
    const bool valid = (group < E);
    const int e = valid ? group : (E - 1);        // clamp; keep warp converged

    const int row = __ldg(ei + e);
    const int col = __ldg(ei + (size_t)E + e);

    const uint4* zr = g_zh + (size_t)row * 16;
    const uint4* zc = g_zh + (size_t)col * 16;
    uint4 A[4], B[4];
    #pragma unroll
    for (int k = 0; k < 4; k++) {
        A[k] = __ldg(zr + k * 4 + l);
        B[k] = __ldg(zc + k * 4 + l);
    }

    unsigned long long dacc = 0ull;
    {
        float2 a, b;
        unsigned long long pa_, pb_;
        #define DOT_STEP(au, bu) \
            a = cvt_h2(au); b = cvt_h2(bu); \
            pa_ = *reinterpret_cast<unsigned long long*>(&a); \
            pb_ = *reinterpret_cast<unsigned long long*>(&b); \
            FMA_F32X2(dacc, pa_, pb_)
        #pragma unroll
        for (int k = 0; k < 4; k++) {
            DOT_STEP(A[k].x, B[k].x);
            DOT_STEP(A[k].y, B[k].y);
            DOT_STEP(A[k].z, B[k].z);
            DOT_STEP(A[k].w, B[k].w);
        }
        #undef DOT_STEP
    }
    float2 dp = *reinterpret_cast<float2*>(&dacc);
    float dot = dp.x + dp.y;

    // MLP head: lane owns hidden units 4l..4l+3 (b1 pre-folded into proj)
    float4 pa = *(const float4*)(g_proj + (size_t)row * 32 + 4 * l);
    float4 pb = *(const float4*)(g_proj + (size_t)col * 32 + 16 + 4 * l);
    float4 w2 = *(const float4*)(W2 + 4 * l);
    float t = fmaxf(pa.x + pb.x, 0.f) * w2.x
            + fmaxf(pa.y + pb.y, 0.f) * w2.y
            + fmaxf(pa.z + pb.z, 0.f) * w2.z
            + fmaxf(pa.w + pb.w, 0.f) * w2.w;

    // reduce (dot, t) together as packed f32x2 over the 4-lane group
    float2 pr = make_float2(dot, t);
    unsigned long long pk = *reinterpret_cast<unsigned long long*>(&pr);
    #pragma unroll
    for (int off = 2; off; off >>= 1) {
        unsigned long long other = __shfl_xor_sync(0xFFFFFFFFu, pk, off);
        ADD_F32X2(pk, pk, other);
    }

    if (l == 0 && valid) {
        float2 r = *reinterpret_cast<float2*>(&pk);
        out[e] = r.x;
        float x = r.y + __ldg(b2);
        // softplus = max(x,0) + log1p(exp(-|x|))
        out[(size_t)E + e] = fmaxf(x, 0.f) + log1pf(__expf(-fabsf(x)));
    }
}

// ---------------- launch ----------------------------------------------------
extern "C" void kernel_launch(void* const* d_in, const int* in_sizes, int n_in,
                              void* d_out, int out_size) {
    const float* z  = (const float*)d_in[0];      // [N,128] f32
    const int*   ei = (const int*)d_in[1];        // [2,E] int32
    const float* W1 = (const float*)d_in[2];      // [256,16]
    const float* b1 = (const float*)d_in[3];      // [16]
    const float* W2 = (const float*)d_in[4];      // [16,1]
    const float* b2 = (const float*)d_in[5];      // [1]
    float* out = (float*)d_out;                   // [2E]: adj_logits | weights

    const int N = in_sizes[0] / 128;
    const int E = in_sizes[1] / 2;

    convert_kernel<<<(N * 16 + 255) / 256, 256>>>(z, W1, N);
    proj_mma_kernel<<<(N + 63) / 64, 128>>>(b1, N);
    edge_kernel<<<((size_t)E * 4 + 255) / 256, 256>>>(ei, W2, b2, out, E);
}